// round 12
// baseline (speedup 1.0000x reference)
#include <cuda_runtime.h>
#include <cuda_fp16.h>
#include <math.h>
#include <float.h>

#define NROWS 200000
#define NBAGS 25000
#define DIM   690
#define NREL  53
#define NPAD  56           // P row stride (cols 53..55 unused)
#define NKS   44           // k16 steps (704 / 16)
#define NJ    7            // n-tiles (56 cols)
#define WCAP  128

// ---------------- scratch (device globals: allocation-free) ----------------
__device__ __align__(16) float g_P[(size_t)NROWS * NPAD];       // 44.8 MB
__device__ __align__(16) uint4 g_Bpack[NKS * NJ * 32];          // 158 KB frag table
__device__ float g_wglob[NROWS];

// ---------------- PTX helpers ----------------
__device__ __forceinline__ void mma_f16(float* c, const unsigned* a, const unsigned* b) {
    asm volatile(
        "mma.sync.aligned.m16n8k16.row.col.f32.f16.f16.f32 "
        "{%0,%1,%2,%3}, {%4,%5,%6,%7}, {%8,%9}, {%0,%1,%2,%3};"
        : "+f"(c[0]), "+f"(c[1]), "+f"(c[2]), "+f"(c[3])
        : "r"(a[0]), "r"(a[1]), "r"(a[2]), "r"(a[3]), "r"(b[0]), "r"(b[1]));
}
__device__ __forceinline__ unsigned packh2(float x, float y) {
    unsigned r;
    asm("cvt.rn.f16x2.f32 %0, %1, %2;" : "=r"(r) : "f"(y), "f"(x));
    return r;
}

// ---------------- K0: pack B = rel into per-lane MMA fragment table --------
// entry (ks, j, lane): n = j*8 + (lane>>2), k = ks*16 + (lane&3)*2
//   .x = hi(B[k],B[k+1])  .y = hi(B[k+8],B[k+9])  .z/.w = fp16 residuals
__global__ void k_prep(const float* __restrict__ rel) {
    int idx = blockIdx.x * blockDim.x + threadIdx.x;
    if (idx >= NKS * NJ * 32) return;
    int ks = idx / (NJ * 32), rem = idx % (NJ * 32);
    int j = rem / 32, lane = rem % 32;
    int n = j * 8 + (lane >> 2);
    int k = ks * 16 + (lane & 3) * 2;
    float v[4] = {0.f, 0.f, 0.f, 0.f};
    if (n < NREL) {
        if (k < DIM)     v[0] = rel[n * DIM + k];
        if (k + 1 < DIM) v[1] = rel[n * DIM + k + 1];
        if (k + 8 < DIM) v[2] = rel[n * DIM + k + 8];
        if (k + 9 < DIM) v[3] = rel[n * DIM + k + 9];
    }
    float h[4], l[4];
#pragma unroll
    for (int i = 0; i < 4; i++) {
        h[i] = __half2float(__float2half(v[i]));
        l[i] = v[i] - h[i];
    }
    uint4 o;
    o.x = packh2(h[0], h[1]);
    o.y = packh2(h[2], h[3]);
    o.z = packh2(l[0], l[1]);
    o.w = packh2(l[2], l[3]);
    g_Bpack[idx] = o;
}

// ---------------- K1: P = repre @ rel^T — barrier-free, smem-free ----------
// one warp per 32-row strip (two m16 fragments); 200000 = 6250 * 32 exactly
__global__ __launch_bounds__(256) void k_pgemm(const float* __restrict__ repre) {
    int wid = threadIdx.x >> 5, lane = threadIdx.x & 31;
    int w = blockIdx.x * 8 + wid;          // strip index
    int row0 = w * 32;
    if (row0 >= NROWS) return;
    int g = lane >> 2, th = lane & 3;
    int r0 = row0 + g;                      // + 0 / 8 / 16 / 24
    const float* p0 = repre + (size_t)r0 * DIM;
    const float* p1 = p0 + (size_t)8  * DIM;
    const float* p2 = p0 + (size_t)16 * DIM;
    const float* p3 = p0 + (size_t)24 * DIM;

    float accA[NJ][4], accB[NJ][4];
#pragma unroll
    for (int j = 0; j < NJ; j++)
#pragma unroll
        for (int q = 0; q < 4; q++) { accA[j][q] = 0.f; accB[j][q] = 0.f; }

    const uint4* bp_lane = g_Bpack + lane;

    // ---- main loop: ks 0..42 fully in-bounds (cols <= 687 < 690) ----
#pragma unroll 2
    for (int ks = 0; ks < NKS - 1; ks++) {
        int c0 = ks * 16 + th * 2;
        int c1 = c0 + 8;
        float2 a0 = *(const float2*)(p0 + c0);
        float2 a1 = *(const float2*)(p1 + c0);
        float2 a2 = *(const float2*)(p0 + c1);
        float2 a3 = *(const float2*)(p1 + c1);
        float2 b0 = *(const float2*)(p2 + c0);
        float2 b1 = *(const float2*)(p3 + c0);
        float2 b2 = *(const float2*)(p2 + c1);
        float2 b3 = *(const float2*)(p3 + c1);
        unsigned fa[4], fb[4];
        fa[0] = packh2(a0.x, a0.y); fa[1] = packh2(a1.x, a1.y);
        fa[2] = packh2(a2.x, a2.y); fa[3] = packh2(a3.x, a3.y);
        fb[0] = packh2(b0.x, b0.y); fb[1] = packh2(b1.x, b1.y);
        fb[2] = packh2(b2.x, b2.y); fb[3] = packh2(b3.x, b3.y);

        const uint4* bp = bp_lane + (size_t)ks * NJ * 32;
#pragma unroll
        for (int j = 0; j < NJ; j++) {
            uint4 b = bp[j * 32];
            unsigned bhi[2] = {b.x, b.y};
            unsigned blo[2] = {b.z, b.w};
            mma_f16(accA[j], fa, bhi);
            mma_f16(accA[j], fa, blo);
            mma_f16(accB[j], fb, bhi);
            mma_f16(accB[j], fb, blo);
        }
    }

    // ---- tail: ks = 43, only cols 688..689 valid (th == 0, first pair) ----
    {
        int ks = NKS - 1;
        int c0 = ks * 16 + th * 2;          // 688 + th*2
        bool v = (c0 + 1 < DIM);            // th == 0 only
        float2 z = make_float2(0.f, 0.f);
        float2 a0 = v ? *(const float2*)(p0 + c0) : z;
        float2 a1 = v ? *(const float2*)(p1 + c0) : z;
        float2 b0 = v ? *(const float2*)(p2 + c0) : z;
        float2 b1 = v ? *(const float2*)(p3 + c0) : z;
        unsigned fa[4], fb[4];
        fa[0] = packh2(a0.x, a0.y); fa[1] = packh2(a1.x, a1.y);
        fa[2] = 0u; fa[3] = 0u;
        fb[0] = packh2(b0.x, b0.y); fb[1] = packh2(b1.x, b1.y);
        fb[2] = 0u; fb[3] = 0u;
        const uint4* bp = bp_lane + (size_t)ks * NJ * 32;
#pragma unroll
        for (int j = 0; j < NJ; j++) {
            uint4 b = bp[j * 32];
            unsigned bhi[2] = {b.x, b.y};
            unsigned blo[2] = {b.z, b.w};
            mma_f16(accA[j], fa, bhi);
            mma_f16(accA[j], fa, blo);
            mma_f16(accB[j], fb, bhi);
            mma_f16(accB[j], fb, blo);
        }
    }

    // ---- epilogue: write P (56 cols; only cols j*8+th*2, +1) ----
    size_t o0 = (size_t)(r0)      * NPAD;   // rows r0, r0+8, r0+16, r0+24
    size_t o1 = (size_t)(r0 + 8)  * NPAD;
    size_t o2 = (size_t)(r0 + 16) * NPAD;
    size_t o3 = (size_t)(r0 + 24) * NPAD;
#pragma unroll
    for (int j = 0; j < NJ; j++) {
        int col = j * 8 + th * 2;
        *(float2*)&g_P[o0 + col] = make_float2(accA[j][0], accA[j][1]);
        *(float2*)&g_P[o1 + col] = make_float2(accA[j][2], accA[j][3]);
        *(float2*)&g_P[o2 + col] = make_float2(accB[j][0], accB[j][1]);
        *(float2*)&g_P[o3 + col] = make_float2(accB[j][2], accB[j][3]);
    }
}

// ---------------- K2: per-bag softmax + combine over P ---------------------
__global__ __launch_bounds__(256) void k_bags(const int* __restrict__ scope,
                                              const int* __restrict__ labels,
                                              const float* __restrict__ bias,
                                              float* __restrict__ out) {
    __shared__ float wbuf[8][WCAP];
    int wid = threadIdx.x >> 5, lane = threadIdx.x & 31;
    int bag = blockIdx.x * 8 + wid;
    if (bag >= NBAGS) return;
    int s = scope[2 * bag];
    int e = scope[2 * bag + 1];
    int c = e - s;
    float* w = (c <= WCAP) ? wbuf[wid] : (g_wglob + s);

    float m = -FLT_MAX;
    for (int i = lane; i < c; i += 32) {
        int gi = s + i;
        float lg = g_P[(size_t)gi * NPAD + labels[gi]];
        w[i] = lg;
        m = fmaxf(m, lg);
    }
#pragma unroll
    for (int o = 16; o; o >>= 1) m = fmaxf(m, __shfl_xor_sync(0xffffffffu, m, o));

    float sum = 0.f;
    for (int i = lane; i < c; i += 32) {
        float ev = __expf(w[i] - m);
        w[i] = ev;
        sum += ev;
    }
#pragma unroll
    for (int o = 16; o; o >>= 1) sum += __shfl_xor_sync(0xffffffffu, sum, o);
    float inv = 1.f / sum;
    __syncwarp();

    int col = lane * 2;
    if (col < NPAD) {    // lanes 0..27
        float2 o2 = make_float2(0.f, 0.f);
        const float* pbase = g_P + (size_t)s * NPAD + col;
#pragma unroll 8
        for (int i = 0; i < c; i++) {
            float wi = w[i] * inv;
            float2 p2 = *(const float2*)(pbase + (size_t)i * NPAD);
            o2.x = fmaf(wi, p2.x, o2.x);
            o2.y = fmaf(wi, p2.y, o2.y);
        }
        if (col < NREL)     out[(size_t)bag * NREL + col]     = o2.x + bias[col];
        if (col + 1 < NREL) out[(size_t)bag * NREL + col + 1] = o2.y + bias[col + 1];
    }
}

// ---------------- launch ----------------
extern "C" void kernel_launch(void* const* d_in, const int* in_sizes, int n_in,
                              void* d_out, int out_size) {
    const float* repre  = (const float*)d_in[0];   // [N, D]
    const float* rel    = (const float*)d_in[1];   // [R, D]
    const float* bias   = (const float*)d_in[2];   // [R]
    const int* scope    = (const int*)d_in[3];     // [NBAGS, 2] int32
    const int* labels   = (const int*)d_in[4];     // [N]        int32
    float* out = (float*)d_out;                    // [NBAGS, R]

    (void)in_sizes; (void)n_in; (void)out_size;

    k_prep<<<(NKS * NJ * 32 + 255) / 256, 256>>>(rel);
    int nstrips = NROWS / 32;                       // 6250
    k_pgemm<<<(nstrips + 7) / 8, 256>>>(repre);
    k_bags<<<(NBAGS + 7) / 8, 256>>>(scope, labels, bias, out);
}